// round 2
// baseline (speedup 1.0000x reference)
#include <cuda_runtime.h>

// Problem constants
#define NROWS   262144        // 16 * 16384
#define DIM     64
#define SUB     256
#define ESTR    68            // padded float stride for E in shared
#define NBLK    1024          // NROWS / 256

// Output layout (float32, tuple flattened in order):
// [z_q_out: 16*64*16384][loss: 1][perplexity: 1][idx: 262144]
#define ZQ_OFF   0
#define LOSS_OFF 16777216
#define PERP_OFF 16777217
#define IDX_OFF  16777218

__device__ int   g_pos;
__device__ float g_enorm[SUB];
__device__ int   g_counts[SUB];
__device__ float g_partial[NBLK];

// ---------------- init: argmax(one_hot), ||e||^2 (serial unfused fp32), zero counts ----------------
__global__ void vq_init(const float* __restrict__ one_hot,
                        const float* __restrict__ W) {
    __shared__ int sp;
    int tid = threadIdx.x;
    if (tid == 0) {
        int p = 0; float m = one_hot[0];
#pragma unroll
        for (int i = 1; i < 7; i++) {
            float v = one_hot[i];
            if (v > m) { m = v; p = i; }   // strict > : first max, matches jnp.argmax
        }
        g_pos = p; sp = p;
    }
    __syncthreads();
    int p = sp;
    const float* Wr = W + ((long)p * SUB + tid) * DIM;
    // Emulate XLA fp32 reduce: serial in-order, mul and add separately rounded.
    float s = 0.f;
#pragma unroll 1
    for (int k = 0; k < DIM; k++) {
        float w = Wr[k];
        s = __fadd_rn(s, __fmul_rn(w, w));
    }
    g_enorm[tid] = s;
    g_counts[tid] = 0;
}

// ---------------- main: exact-rounding-emulated distances + argmin + outputs ----------------
__global__ __launch_bounds__(256, 2)
void vq_main(const float* __restrict__ z,
             const float* __restrict__ W,
             float* __restrict__ out) {
    extern __shared__ float sm[];
    float* Es   = sm;                         // SUB * ESTR floats
    float* en   = sm + SUB * ESTR;            // SUB floats (||e||^2, XLA-rounded)
    int*   sidx = (int*)(en + SUB);           // SUB ints (unused by others, kept for debug)
    __shared__ float red[256];

    const int tid = threadIdx.x;
    const int pos = g_pos;
    const float* Wp = W + (long)pos * SUB * DIM;

    // stage E (256 x 64) into shared with padded stride
    for (int i = tid; i < SUB * 16; i += 256) {
        int r = i >> 4, c = i & 15;
        float4 v = ((const float4*)Wp)[r * 16 + c];
        *(float4*)&Es[r * ESTR + c * 4] = v;
    }
    en[tid] = g_enorm[tid];

    // this thread's z row into registers
    const long row = (long)blockIdx.x * 256 + tid;
    float zr[64];
    {
        const float4* zp = (const float4*)(z + row * DIM);
#pragma unroll
        for (int k = 0; k < 16; k++) {
            float4 v = zp[k];
            zr[4 * k + 0] = v.x; zr[4 * k + 1] = v.y;
            zr[4 * k + 2] = v.z; zr[4 * k + 3] = v.w;
        }
    }

    // zz = ||z||^2 : serial in-order, unfused (emulates XLA CPU fp32 reduce)
    float zz = 0.f;
#pragma unroll 1
    for (int k = 0; k < 64; k++) {
        zz = __fadd_rn(zz, __fmul_rn(zr[k], zr[k]));
    }

    __syncthreads();

    // d_c = R( R(zz + ee_c) - 2 * ze_c ), ze_c = serial ascending fused-FMA chain
    // argmin with strict < over ascending c == first-min (jnp.argmin tie-break)
    float best = 3.402823466e38f;
    int bi = 0;
#pragma unroll 1
    for (int c = 0; c < SUB; c += 4) {
        const float* e0 = Es + (c + 0) * ESTR;
        const float* e1 = Es + (c + 1) * ESTR;
        const float* e2 = Es + (c + 2) * ESTR;
        const float* e3 = Es + (c + 3) * ESTR;
        float a0 = 0.f, a1 = 0.f, a2 = 0.f, a3 = 0.f;
#pragma unroll
        for (int k = 0; k < 64; k += 4) {
            float4 q0 = *(const float4*)(e0 + k);
            float4 q1 = *(const float4*)(e1 + k);
            float4 q2 = *(const float4*)(e2 + k);
            float4 q3 = *(const float4*)(e3 + k);
            a0 = __fmaf_rn(zr[k + 0], q0.x, a0);
            a1 = __fmaf_rn(zr[k + 0], q1.x, a1);
            a2 = __fmaf_rn(zr[k + 0], q2.x, a2);
            a3 = __fmaf_rn(zr[k + 0], q3.x, a3);
            a0 = __fmaf_rn(zr[k + 1], q0.y, a0);
            a1 = __fmaf_rn(zr[k + 1], q1.y, a1);
            a2 = __fmaf_rn(zr[k + 1], q2.y, a2);
            a3 = __fmaf_rn(zr[k + 1], q3.y, a3);
            a0 = __fmaf_rn(zr[k + 2], q0.z, a0);
            a1 = __fmaf_rn(zr[k + 2], q1.z, a1);
            a2 = __fmaf_rn(zr[k + 2], q2.z, a2);
            a3 = __fmaf_rn(zr[k + 2], q3.z, a3);
            a0 = __fmaf_rn(zr[k + 3], q0.w, a0);
            a1 = __fmaf_rn(zr[k + 3], q1.w, a1);
            a2 = __fmaf_rn(zr[k + 3], q2.w, a2);
            a3 = __fmaf_rn(zr[k + 3], q3.w, a3);
        }
        // 2*ze is exact (x2); reference does t = R(zz+ee) then R(t - 2ze):
        // single-rounded fused t + (-2)*a is identical because 2*a is exact.
        float d0 = __fmaf_rn(-2.f, a0, __fadd_rn(zz, en[c + 0]));
        float d1 = __fmaf_rn(-2.f, a1, __fadd_rn(zz, en[c + 1]));
        float d2 = __fmaf_rn(-2.f, a2, __fadd_rn(zz, en[c + 2]));
        float d3 = __fmaf_rn(-2.f, a3, __fadd_rn(zz, en[c + 3]));
        if (d0 < best) { best = d0; bi = c + 0; }
        if (d1 < best) { best = d1; bi = c + 1; }
        if (d2 < best) { best = d2; bi = c + 2; }
        if (d3 < best) { best = d3; bi = c + 3; }
    }

    sidx[tid] = bi;
    atomicAdd(&g_counts[bi], 1);
    out[IDX_OFF + row] = (float)bi;

    // loss partial: sum_d (z_d - e_d)^2   (scalar output, loose tolerance)
    // and straight-through zq into zr: zq = R(z + R(e - z)) elementwise (matches ref)
    {
        const float* eb = Es + bi * ESTR;
        float s = 0.f;
#pragma unroll
        for (int k = 0; k < 64; k++) {
            float e  = eb[k];
            float df = __fsub_rn(e, zr[k]);       // z_q - z
            s += df * df;
            zr[k] = __fadd_rn(zr[k], df);         // z + (z_q - z)
        }
        red[tid] = s;
    }
    __syncthreads();
#pragma unroll
    for (int o = 128; o; o >>= 1) {
        if (tid < o) red[tid] += red[tid + o];
        __syncthreads();
    }
    if (tid == 0) g_partial[blockIdx.x] = red[0];

    // transposed straight-through output: out[b, d, t] — each thread owns a full
    // row in registers, so lane index == t gives naturally coalesced stores.
    {
        const int b  = (int)(row >> 14);          // row / 16384
        const int t  = (int)(row & 16383);        // t index within batch
        float* zo = out + ZQ_OFF + (long)b * DIM * 16384 + t;
#pragma unroll
        for (int k = 0; k < 64; k++) {
            zo[(long)k * 16384] = zr[k];
        }
    }
}

// ---------------- final: loss scalar + perplexity ----------------
__global__ void vq_final(float* __restrict__ out) {
    __shared__ float red[256];
    int tid = threadIdx.x;

    // deterministic sum of per-block loss partials
    float s = g_partial[tid] + g_partial[tid + 256]
            + g_partial[tid + 512] + g_partial[tid + 768];
    red[tid] = s;
    __syncthreads();
#pragma unroll
    for (int o = 128; o; o >>= 1) {
        if (tid < o) red[tid] += red[tid + o];
        __syncthreads();
    }
    float total = red[0];
    __syncthreads();

    // entropy over e_mean  (counts exact ints; /2^18 exact)
    float c  = (float)g_counts[tid];
    float em = c * (1.0f / 262144.0f);
    float term = em * logf(em + 1e-10f);
    red[tid] = term;
    __syncthreads();
#pragma unroll
    for (int o = 128; o; o >>= 1) {
        if (tid < o) red[tid] += red[tid + o];
        __syncthreads();
    }
    if (tid == 0) {
        out[LOSS_OFF] = 1.25f * total * (1.0f / 16777216.0f);
        out[PERP_OFF] = expf(-red[0]);
    }
}

extern "C" void kernel_launch(void* const* d_in, const int* in_sizes, int n_in,
                              void* d_out, int out_size) {
    const float* z       = (const float*)d_in[0];
    const float* one_hot = (const float*)d_in[1];
    const float* W       = (const float*)d_in[2];
    float* out = (float*)d_out;

    size_t smem = (size_t)(SUB * ESTR + SUB) * sizeof(float) + SUB * sizeof(int);
    cudaFuncSetAttribute(vq_main, cudaFuncAttributeMaxDynamicSharedMemorySize, (int)smem);

    vq_init<<<1, 256>>>(one_hot, W);
    vq_main<<<NBLK, 256, smem>>>(z, W, out);
    vq_final<<<1, 256>>>(out);
}

// round 3
// speedup vs baseline: 1.0768x; 1.0768x over previous
#include <cuda_runtime.h>

// Problem constants
#define NROWS   262144        // 16 * 16384
#define DIM     64
#define SUB     256
#define NBLK    1024          // NROWS / 256

// Output layout (float32, tuple flattened in order):
// [z_q_out: 16*64*16384][loss: 1][perplexity: 1][idx: 262144]
#define ZQ_OFF   0
#define LOSS_OFF 16777216
#define PERP_OFF 16777217
#define IDX_OFF  16777218

__device__ int   g_counts[SUB];
__device__ float g_partial[NBLK];

// packed f32x2 FMA: each lane is an independent IEEE fp32 fused FMA chain
__device__ __forceinline__ void fma2(unsigned long long& d,
                                     unsigned long long a,
                                     unsigned long long b) {
    asm("fma.rn.f32x2 %0, %1, %2, %0;" : "+l"(d) : "l"(a), "l"(b));
}

union ZP { unsigned long long u; float2 f; };

// ---------------- tiny init: zero the histogram ----------------
__global__ void vq_zero() { g_counts[threadIdx.x] = 0; }

// ---------------- main: distances (code-pair-packed FFMA2) + argmin + outputs ----------------
__global__ __launch_bounds__(256, 1)
void vq_main(const float* __restrict__ z,
             const float* __restrict__ one_hot,
             const float* __restrict__ W,
             float* __restrict__ out) {
    __shared__ float EsT[DIM * SUB];   // transposed: EsT[k*256 + c]  (64 KB)
    __shared__ float en[SUB];          // ||e||^2, XLA-serial-unfused rounding
    __shared__ float red[256];
    __shared__ int   sp;

    const int tid = threadIdx.x;

    // pos = argmax(one_hot) — recomputed per block (7 L2-hit reads)
    if (tid == 0) {
        int p = 0; float m = one_hot[0];
#pragma unroll
        for (int i = 1; i < 7; i++) {
            float v = one_hot[i];
            if (v > m) { m = v; p = i; }   // strict > : first max == jnp.argmax
        }
        sp = p;
    }

    // start z row loads early (independent of sp)
    const long row = (long)blockIdx.x * 256 + tid;
    ZP z2[64];                           // packed {z_k, z_k}; .f.x is the scalar view
    {
        const float4* zp = (const float4*)(z + row * DIM);
#pragma unroll
        for (int k = 0; k < 16; k++) {
            float4 v = zp[k];
            z2[4 * k + 0].f = make_float2(v.x, v.x);
            z2[4 * k + 1].f = make_float2(v.y, v.y);
            z2[4 * k + 2].f = make_float2(v.z, v.z);
            z2[4 * k + 3].f = make_float2(v.w, v.w);
        }
    }

    __syncthreads();
    const int pos = sp;
    const float* Wp = W + (long)pos * SUB * DIM;

    // stage E transposed: thread t owns code t (coalesced-enough reads, conflict-free STS)
    // and computes en[t] with the XLA serial unfused chain.
    {
        const float4* wr = (const float4*)(Wp + tid * DIM);
        float s = 0.f;
#pragma unroll
        for (int j = 0; j < 16; j++) {
            float4 v = wr[j];
            EsT[(4 * j + 0) * SUB + tid] = v.x;
            EsT[(4 * j + 1) * SUB + tid] = v.y;
            EsT[(4 * j + 2) * SUB + tid] = v.z;
            EsT[(4 * j + 3) * SUB + tid] = v.w;
            s = __fadd_rn(s, __fmul_rn(v.x, v.x));
            s = __fadd_rn(s, __fmul_rn(v.y, v.y));
            s = __fadd_rn(s, __fmul_rn(v.z, v.z));
            s = __fadd_rn(s, __fmul_rn(v.w, v.w));
        }
        en[tid] = s;
    }

    // zz = ||z||^2 : serial in-order, unfused (XLA CPU fp32 reduce emulation)
    float zz = 0.f;
#pragma unroll
    for (int k = 0; k < 64; k++) {
        zz = __fadd_rn(zz, __fmul_rn(z2[k].f.x, z2[k].f.x));
    }

    __syncthreads();

    // d_c = R( R(zz + ee_c) - 2*ze_c ); ze_c = serial ascending fused-FMA chain.
    // Codes packed pairwise in f32x2 lanes — each lane's chain is bit-identical
    // to the scalar version. 8 codes (4 packed accums) per group for ILP.
    float best = 3.402823466e38f;
    int bi = 0;
#pragma unroll 1
    for (int c = 0; c < SUB; c += 8) {
        unsigned long long p0 = 0ull, p1 = 0ull, p2 = 0ull, p3 = 0ull;
        const char* bp = (const char*)(EsT + c);
#pragma unroll
        for (int k = 0; k < 64; k++) {
            ulonglong2 qa = *(const ulonglong2*)(bp + (size_t)k * (SUB * 4));
            ulonglong2 qb = *(const ulonglong2*)(bp + (size_t)k * (SUB * 4) + 16);
            fma2(p0, z2[k].u, qa.x);   // codes c,   c+1
            fma2(p1, z2[k].u, qa.y);   // codes c+2, c+3
            fma2(p2, z2[k].u, qb.x);   // codes c+4, c+5
            fma2(p3, z2[k].u, qb.y);   // codes c+6, c+7
        }
        ZP u0, u1, u2, u3;
        u0.u = p0; u1.u = p1; u2.u = p2; u3.u = p3;
        float d0 = __fmaf_rn(-2.f, u0.f.x, __fadd_rn(zz, en[c + 0]));
        float d1 = __fmaf_rn(-2.f, u0.f.y, __fadd_rn(zz, en[c + 1]));
        float d2 = __fmaf_rn(-2.f, u1.f.x, __fadd_rn(zz, en[c + 2]));
        float d3 = __fmaf_rn(-2.f, u1.f.y, __fadd_rn(zz, en[c + 3]));
        float d4 = __fmaf_rn(-2.f, u2.f.x, __fadd_rn(zz, en[c + 4]));
        float d5 = __fmaf_rn(-2.f, u2.f.y, __fadd_rn(zz, en[c + 5]));
        float d6 = __fmaf_rn(-2.f, u3.f.x, __fadd_rn(zz, en[c + 6]));
        float d7 = __fmaf_rn(-2.f, u3.f.y, __fadd_rn(zz, en[c + 7]));
        if (d0 < best) { best = d0; bi = c + 0; }
        if (d1 < best) { best = d1; bi = c + 1; }
        if (d2 < best) { best = d2; bi = c + 2; }
        if (d3 < best) { best = d3; bi = c + 3; }
        if (d4 < best) { best = d4; bi = c + 4; }
        if (d5 < best) { best = d5; bi = c + 5; }
        if (d6 < best) { best = d6; bi = c + 6; }
        if (d7 < best) { best = d7; bi = c + 7; }
    }

    atomicAdd(&g_counts[bi], 1);
    out[IDX_OFF + row] = (float)bi;

    // loss partial + straight-through zq in place:
    // zq = R(z + R(e - z)) elementwise (matches reference rounding exactly)
    {
        float s = 0.f;
#pragma unroll
        for (int k = 0; k < 64; k++) {
            float e  = EsT[k * SUB + bi];
            float zk = z2[k].f.x;
            float df = __fsub_rn(e, zk);          // z_q - z
            s += df * df;
            z2[k].f.x = __fadd_rn(zk, df);        // z + (z_q - z)
        }
        red[tid] = s;
    }
    __syncthreads();
#pragma unroll
    for (int o = 128; o; o >>= 1) {
        if (tid < o) red[tid] += red[tid + o];
        __syncthreads();
    }
    if (tid == 0) g_partial[blockIdx.x] = red[0];

    // transposed output out[b, d, t]: lane index == t -> coalesced stores
    {
        const int b = (int)(row >> 14);
        const int t = (int)(row & 16383);
        float* zo = out + ZQ_OFF + (long)b * DIM * 16384 + t;
#pragma unroll
        for (int k = 0; k < 64; k++) {
            zo[(long)k * 16384] = z2[k].f.x;
        }
    }
}

// ---------------- final: loss scalar + perplexity ----------------
__global__ void vq_final(float* __restrict__ out) {
    __shared__ float red[256];
    int tid = threadIdx.x;

    float s = g_partial[tid] + g_partial[tid + 256]
            + g_partial[tid + 512] + g_partial[tid + 768];
    red[tid] = s;
    __syncthreads();
#pragma unroll
    for (int o = 128; o; o >>= 1) {
        if (tid < o) red[tid] += red[tid + o];
        __syncthreads();
    }
    float total = red[0];
    __syncthreads();

    float c  = (float)g_counts[tid];
    float em = c * (1.0f / 262144.0f);
    float term = em * logf(em + 1e-10f);
    red[tid] = term;
    __syncthreads();
#pragma unroll
    for (int o = 128; o; o >>= 1) {
        if (tid < o) red[tid] += red[tid + o];
        __syncthreads();
    }
    if (tid == 0) {
        out[LOSS_OFF] = 1.25f * total * (1.0f / 16777216.0f);
        out[PERP_OFF] = expf(-red[0]);
    }
}

extern "C" void kernel_launch(void* const* d_in, const int* in_sizes, int n_in,
                              void* d_out, int out_size) {
    const float* z       = (const float*)d_in[0];
    const float* one_hot = (const float*)d_in[1];
    const float* W       = (const float*)d_in[2];
    float* out = (float*)d_out;

    vq_zero<<<1, 256>>>();
    vq_main<<<NBLK, 256>>>(z, one_hot, W, out);
    vq_final<<<1, 256>>>(out);
}